// round 12
// baseline (speedup 1.0000x reference)
#include <cuda_runtime.h>
#include <cuda_bf16.h>
#include <math.h>

// Problem constants (fixed by the dataset)
#define NN    50000
#define DEG   16
#define EDGES (NN * DEG)      // 800000
#define DIM   128
#define HID   128

#define NPB   8               // nodes per block (kernel 2)
#define EPB   128             // edges per block
#define K2T   256             // threads (kernel 2)
#define H1SR  132             // h1T row stride (floats)

typedef unsigned long long ull;

#define FMA_F32X2(acc, a, b) \
    asm("fma.rn.f32x2 %0, %1, %2, %0;" : "+l"(acc) : "l"(a), "l"(b))
#define PACK_F32X2(out, lo, hi) \
    asm("mov.b64 %0, {%1, %2};" : "=l"(out) : "r"(lo), "r"(hi))
#define UNPACK_F32X2(lo, hi, in) \
    asm("mov.b64 {%0, %1}, %2;" : "=r"(lo), "=r"(hi) : "l"(in))

// Persistent scratch: layer-1 node projections A = F @ W1[0:128], B = F @ W1[128:256]
__device__ float g_A[NN * DIM];
__device__ float g_B[NN * DIM];

// Layer-2 weights in constant memory (warp-uniform -> const port)
__constant__ float c_w2[HID * HID];   // 64 KB

// ---------------------------------------------------------------------------
// Kernel 1: AB = features[N,128] @ Wcat[128,256]. Tiled fp32 GEMM. (proven)
// ---------------------------------------------------------------------------
#define K1_SMEM_FLOATS (64 * 132 + 128 * 68)

__global__ void layer1_gemm_kernel(const float* __restrict__ feat,
                                   const float* __restrict__ w1) {
    extern __shared__ float smem1[];
    float* featS = smem1;              // [64][132]
    float* wS    = smem1 + 64 * 132;   // [128][68]

    const int tid = threadIdx.x;
    const int m0 = blockIdx.x * 64;
    const int n0 = blockIdx.y * 64;

    for (int t = tid; t < 64 * 32; t += 256) {
        int r = t >> 5, c4 = (t & 31) << 2;
        int gr = m0 + r;
        float4 v = make_float4(0.f, 0.f, 0.f, 0.f);
        if (gr < NN) v = *(const float4*)&feat[gr * DIM + c4];
        *(float4*)&featS[r * 132 + c4] = v;
    }
    for (int t = tid; t < 128 * 16; t += 256) {
        int k = t >> 4, c4 = (t & 15) << 2;
        int n = n0 + c4;
        const float* src = (n < 128) ? &w1[k * 128 + n]
                                     : &w1[(128 + k) * 128 + (n - 128)];
        *(float4*)&wS[k * 68 + c4] = *(const float4*)src;
    }
    __syncthreads();

    const int ty = tid >> 4, tx = tid & 15;
    const int r0 = ty * 4, c0 = tx * 4;
    float acc[4][4];
#pragma unroll
    for (int i = 0; i < 4; ++i)
#pragma unroll
        for (int j = 0; j < 4; ++j) acc[i][j] = 0.f;

#pragma unroll 4
    for (int k = 0; k < 128; ++k) {
        float a[4];
#pragma unroll
        for (int i = 0; i < 4; ++i) a[i] = featS[(r0 + i) * 132 + k];
        float4 bq = *(const float4*)&wS[k * 68 + c0];
        float b[4] = {bq.x, bq.y, bq.z, bq.w};
#pragma unroll
        for (int i = 0; i < 4; ++i)
#pragma unroll
            for (int j = 0; j < 4; ++j) acc[i][j] = fmaf(a[i], b[j], acc[i][j]);
    }

#pragma unroll
    for (int i = 0; i < 4; ++i) {
        int node = m0 + r0 + i;
        if (node >= NN) continue;
        int n = n0 + c0;
        float4 o = make_float4(acc[i][0], acc[i][1], acc[i][2], acc[i][3]);
        if (n < 128) *(float4*)&g_A[node * DIM + n] = o;
        else         *(float4*)&g_B[node * DIM + (n - 128)] = o;
    }
}

// ---------------------------------------------------------------------------
// Kernel 2: per block = 8 nodes = 128 edges, 256 threads, 3 blocks/SM.
//  Phase 1: h1T[j][el] = relu(A[row]+B[col]+v*w1[256,j]+b1[j])
//  Phase 2: packed f32x2 FMAs; tile 4 edges x 8 cols, two col-passes/warp
//           (acc=16 ull -> regs freed for ptxas pipelining); b from const.
//  Phase 3: per-node softmax -> hard-concrete -> softmax -> top-8 mask.
// ---------------------------------------------------------------------------
#define K2_SMEM_FLOATS (128 * H1SR + EPB * 9 + 4 * 128 + 3 * EPB)

__global__ void __launch_bounds__(K2T, 3)
edge_mlp_mask_kernel(const int* __restrict__ colIdx,
                     const float* __restrict__ values,
                     const float* __restrict__ temperature,
                     const float* __restrict__ w1,
                     const float* __restrict__ b1,
                     const float* __restrict__ b2,
                     const float* __restrict__ w3,
                     const float* __restrict__ b3,
                     float* __restrict__ out) {
    extern __shared__ float smem[];
    float* h1T   = smem;                      // [128(j)][132]
    float* zred  = h1T + 128 * H1SR;          // [128(el)][9]
    float* b2s   = zred + EPB * 9;            // [128]
    float* w3s   = b2s + 128;                 // [128]
    float* b1s   = w3s + 128;                 // [128]
    float* w1rs  = b1s + 128;                 // [128]
    float* vals  = w1rs + 128;                // [128]
    float* zz    = vals + EPB;                // [128]
    int*   cols  = (int*)(zz + EPB);          // [128]

    const int tid = threadIdx.x;
    const int wid = tid >> 5;
    const int lane = tid & 31;
    const int base_node = blockIdx.x * NPB;
    const int e0 = blockIdx.x * EPB;

    // ---- stage b1/b2/w3, w1 value-row, colIdx, values ----
    if (tid < 128) {
        b2s[tid]  = b2[tid];
        w3s[tid]  = w3[tid];
        b1s[tid]  = b1[tid];
        w1rs[tid] = w1[256 * 128 + tid];
    } else {
        int t2 = tid - 128;
        cols[t2] = colIdx[e0 + t2];
        vals[t2] = values[e0 + t2];
    }
    __syncthreads();

    // ---- Phase 1: j across lanes (coalesced g_B rows), float4 stores ----
    {
        const int j = tid & 127;
        const int g = tid >> 7;
        const float b1j = b1s[j];
        const float wrj = w1rs[j];
#pragma unroll
        for (int nn = 0; nn < 4; ++nn) {
            const int node = g * 4 + nn;
            const float a = g_A[(base_node + node) * DIM + j] + b1j;
#pragma unroll
            for (int q = 0; q < 4; ++q) {
                const int el = node * 16 + q * 4;
                int4   c4 = *(const int4*)&cols[el];
                float4 v4 = *(const float4*)&vals[el];
                float4 h;
                h.x = fmaf(v4.x, wrj, a + g_B[c4.x * DIM + j]);
                h.y = fmaf(v4.y, wrj, a + g_B[c4.y * DIM + j]);
                h.z = fmaf(v4.z, wrj, a + g_B[c4.z * DIM + j]);
                h.w = fmaf(v4.w, wrj, a + g_B[c4.w * DIM + j]);
                h.x = fmaxf(h.x, 0.f); h.y = fmaxf(h.y, 0.f);
                h.z = fmaxf(h.z, 0.f); h.w = fmaxf(h.w, 0.f);
                *(float4*)&h1T[j * H1SR + el] = h;
            }
        }
    }
    __syncthreads();

    // ---- Phase 2: f32x2 GEMM; warp = 16 cols in two 8-col passes ----
    {
        const int er0 = lane * 4;               // 4 consecutive edges
        float spart[4] = {0.f, 0.f, 0.f, 0.f};  // w3 partial dot per edge

#pragma unroll
        for (int pass = 0; pass < 2; ++pass) {
            const int jc0 = wid * 16 + pass * 8;   // 8 cols = 4 pairs

            ull acc[4][4];
#pragma unroll
            for (int i = 0; i < 4; ++i)
#pragma unroll
                for (int p = 0; p < 4; ++p) acc[i][p] = 0ull;

#pragma unroll 4
            for (int k = 0; k < 128; ++k) {
                float4 a4 = *(const float4*)&h1T[k * H1SR + er0];
                const ulonglong2* wp = (const ulonglong2*)&c_w2[k * 128 + jc0];
                ulonglong2 b01 = wp[0], b23 = wp[1];

                ull pa[4];
                PACK_F32X2(pa[0], __float_as_uint(a4.x), __float_as_uint(a4.x));
                PACK_F32X2(pa[1], __float_as_uint(a4.y), __float_as_uint(a4.y));
                PACK_F32X2(pa[2], __float_as_uint(a4.z), __float_as_uint(a4.z));
                PACK_F32X2(pa[3], __float_as_uint(a4.w), __float_as_uint(a4.w));

                ull pb[4];
                pb[0] = b01.x; pb[1] = b01.y;
                pb[2] = b23.x; pb[3] = b23.y;
#pragma unroll
                for (int i = 0; i < 4; ++i)
#pragma unroll
                    for (int p = 0; p < 4; ++p)
                        FMA_F32X2(acc[i][p], pa[i], pb[p]);
            }

            // epilogue (ascending cols within pass; pass 0 then 1 => ascending)
#pragma unroll
            for (int i = 0; i < 4; ++i) {
                float s = spart[i];
#pragma unroll
                for (int p = 0; p < 4; ++p) {
                    unsigned lo, hi;
                    UNPACK_F32X2(lo, hi, acc[i][p]);
                    float h2a = fmaxf(__uint_as_float(lo) + b2s[jc0 + 2 * p], 0.f);
                    s = fmaf(h2a, w3s[jc0 + 2 * p], s);
                    float h2b = fmaxf(__uint_as_float(hi) + b2s[jc0 + 2 * p + 1], 0.f);
                    s = fmaf(h2b, w3s[jc0 + 2 * p + 1], s);
                }
                spart[i] = s;
            }
        }
#pragma unroll
        for (int i = 0; i < 4; ++i)
            zred[(er0 + i) * 9 + wid] = spart[i];
    }
    __syncthreads();

    if (tid < EPB) {
        float s = b3[0];
#pragma unroll
        for (int g = 0; g < 8; ++g) s += zred[tid * 9 + g];
        zz[tid] = s;
    }
    __syncthreads();

    // ---- Phase 3: warp w -> node w (8 warps), exact proven chain ----
    {
        const unsigned FULL = 0xffffffffu;
        const int l = lane & 15;
        const int el = wid * 16 + l;
        const float zv = zz[el];

        float m = zv;
#pragma unroll
        for (int o = 8; o >= 1; o >>= 1) m = fmaxf(m, __shfl_xor_sync(FULL, m, o, 16));
        float x1 = __fsub_rn(zv, m);
        float ev = (float)exp((double)x1);
        float s = 0.f;
#pragma unroll
        for (int o = 0; o < 16; ++o) s = __fadd_rn(s, __shfl_sync(FULL, ev, o, 16));
        float pi = __fdiv_rn(ev, s);

        float larg = __fadd_rn(pi, 1e-8f);
        float lg = (float)log((double)larg);
        float sx = __fdiv_rn(lg, temperature[0]);
        float hard = (float)(1.0 / (1.0 + exp(-(double)sx)));
        hard = fminf(fmaxf(hard, 0.f), 1.f);

        float m2 = hard;
#pragma unroll
        for (int o = 8; o >= 1; o >>= 1) m2 = fmaxf(m2, __shfl_xor_sync(FULL, m2, o, 16));
        float x2 = __fsub_rn(hard, m2);
        float e2 = (float)exp((double)x2);
        float s2 = 0.f;
#pragma unroll
        for (int o = 0; o < 16; ++o) s2 = __fadd_rn(s2, __shfl_sync(FULL, e2, o, 16));
        float y = __fdiv_rn(e2, s2);

        int r = 0;
#pragma unroll
        for (int o = 0; o < 16; ++o) {
            float yo = __shfl_sync(FULL, y, o, 16);
            r += (yo > y) || (yo == y && o < l);
        }
        unsigned bal = __ballot_sync(FULL, (r == 7) && (lane < 16));
        int src = __ffs(bal) - 1;
        float thre = __shfl_sync(FULL, y, src);

        float t = __fadd_rn(__fsub_rn(y, thre), 1e-7f);
        float outv = (t > 0.f) ? y : 0.f;
        if (lane < 16) out[e0 + el] = outv;
    }
}

// ---------------------------------------------------------------------------
extern "C" void kernel_launch(void* const* d_in, const int* in_sizes, int n_in,
                              void* d_out, int out_size) {
    const float* feat        = (const float*)d_in[0];
    const int*   indices     = (const int*)d_in[1];   // [2, E]
    const float* values      = (const float*)d_in[2]; // [E, 1]
    const float* temperature = (const float*)d_in[3];
    const float* w1          = (const float*)d_in[4]; // [257, 128]
    const float* b1          = (const float*)d_in[5];
    const float* w2          = (const float*)d_in[6]; // [128, 128]
    const float* b2          = (const float*)d_in[7];
    const float* w3          = (const float*)d_in[8]; // [128, 1]
    const float* b3          = (const float*)d_in[9];
    float* out = (float*)d_out;

    const int* colIdx = indices + EDGES;  // indices[1]

    // stage w2 into constant memory (device-to-device, graph-capturable)
    cudaMemcpyToSymbolAsync(c_w2, w2, HID * HID * sizeof(float), 0,
                            cudaMemcpyDeviceToDevice);

    const size_t smem1 = K1_SMEM_FLOATS * sizeof(float);
    const size_t smem2 = K2_SMEM_FLOATS * sizeof(float);
    cudaFuncSetAttribute(layer1_gemm_kernel,
                         cudaFuncAttributeMaxDynamicSharedMemorySize, (int)smem1);
    cudaFuncSetAttribute(edge_mlp_mask_kernel,
                         cudaFuncAttributeMaxDynamicSharedMemorySize, (int)smem2);

    dim3 g1((NN + 63) / 64, 2 * DIM / 64);  // 782 x 4
    layer1_gemm_kernel<<<g1, 256, smem1>>>(feat, w1);

    edge_mlp_mask_kernel<<<EDGES / EPB, K2T, smem2>>>(
        colIdx, values, temperature, w1, b1, b2, w3, b3, out);
}

// round 13
// speedup vs baseline: 1.4080x; 1.4080x over previous
#include <cuda_runtime.h>
#include <cuda_bf16.h>
#include <math.h>

// Problem constants (fixed by the dataset)
#define NN    50000
#define DEG   16
#define EDGES (NN * DEG)      // 800000
#define DIM   128
#define HID   128

#define NPB   8               // nodes per block (kernel 2)
#define EPB   128             // edges per block
#define K2T   512             // threads (kernel 2)
#define H1SR  132             // h1T row stride (floats)

typedef unsigned long long ull;

#define FMA_F32X2(acc, a, b) \
    asm("fma.rn.f32x2 %0, %1, %2, %0;" : "+l"(acc) : "l"(a), "l"(b))
#define PACK_F32X2(out, lo, hi) \
    asm("mov.b64 %0, {%1, %2};" : "=l"(out) : "r"(lo), "r"(hi))
#define UNPACK_F32X2(lo, hi, in) \
    asm("mov.b64 {%0, %1}, %2;" : "=r"(lo), "=r"(hi) : "l"(in))

// Persistent scratch: layer-1 node projections A = F @ W1[0:128], B = F @ W1[128:256]
__device__ float g_A[NN * DIM];
__device__ float g_B[NN * DIM];

// Layer-2 weights in constant memory (warp-uniform -> const port)
__constant__ float c_w2[HID * HID];   // 64 KB

// ---------------------------------------------------------------------------
// Kernel 1: AB = features[N,128] @ Wcat[128,256]. Tiled fp32 GEMM. (proven)
// ---------------------------------------------------------------------------
#define K1_SMEM_FLOATS (64 * 132 + 128 * 68)

__global__ void layer1_gemm_kernel(const float* __restrict__ feat,
                                   const float* __restrict__ w1) {
    extern __shared__ float smem1[];
    float* featS = smem1;              // [64][132]
    float* wS    = smem1 + 64 * 132;   // [128][68]

    const int tid = threadIdx.x;
    const int m0 = blockIdx.x * 64;
    const int n0 = blockIdx.y * 64;

    for (int t = tid; t < 64 * 32; t += 256) {
        int r = t >> 5, c4 = (t & 31) << 2;
        int gr = m0 + r;
        float4 v = make_float4(0.f, 0.f, 0.f, 0.f);
        if (gr < NN) v = *(const float4*)&feat[gr * DIM + c4];
        *(float4*)&featS[r * 132 + c4] = v;
    }
    for (int t = tid; t < 128 * 16; t += 256) {
        int k = t >> 4, c4 = (t & 15) << 2;
        int n = n0 + c4;
        const float* src = (n < 128) ? &w1[k * 128 + n]
                                     : &w1[(128 + k) * 128 + (n - 128)];
        *(float4*)&wS[k * 68 + c4] = *(const float4*)src;
    }
    __syncthreads();

    const int ty = tid >> 4, tx = tid & 15;
    const int r0 = ty * 4, c0 = tx * 4;
    float acc[4][4];
#pragma unroll
    for (int i = 0; i < 4; ++i)
#pragma unroll
        for (int j = 0; j < 4; ++j) acc[i][j] = 0.f;

#pragma unroll 4
    for (int k = 0; k < 128; ++k) {
        float a[4];
#pragma unroll
        for (int i = 0; i < 4; ++i) a[i] = featS[(r0 + i) * 132 + k];
        float4 bq = *(const float4*)&wS[k * 68 + c0];
        float b[4] = {bq.x, bq.y, bq.z, bq.w};
#pragma unroll
        for (int i = 0; i < 4; ++i)
#pragma unroll
            for (int j = 0; j < 4; ++j) acc[i][j] = fmaf(a[i], b[j], acc[i][j]);
    }

#pragma unroll
    for (int i = 0; i < 4; ++i) {
        int node = m0 + r0 + i;
        if (node >= NN) continue;
        int n = n0 + c0;
        float4 o = make_float4(acc[i][0], acc[i][1], acc[i][2], acc[i][3]);
        if (n < 128) *(float4*)&g_A[node * DIM + n] = o;
        else         *(float4*)&g_B[node * DIM + (n - 128)] = o;
    }
}

// ---------------------------------------------------------------------------
// Kernel 2: per block = 8 nodes = 128 edges, 512 threads, 2 blocks/SM.
//  Phase 1: h1T[j][el] = relu(A[row]+B[col]+v*w1[256,j]+b1[j])
//  Phase 2: f32x2 GEMM; thread tile 2 edges x 16 cols (acc = 32 regs) so
//           2 blocks x 16 warps = 32 warps/SM hide the LDS/LDC chains.
//  Phase 3: per-node softmax -> hard-concrete -> softmax -> top-8 mask.
// ---------------------------------------------------------------------------
#define K2_SMEM_FLOATS (128 * H1SR + EPB * 9 + 4 * 128 + 3 * EPB)

__global__ void __launch_bounds__(K2T, 2)
edge_mlp_mask_kernel(const int* __restrict__ colIdx,
                     const float* __restrict__ values,
                     const float* __restrict__ temperature,
                     const float* __restrict__ w1,
                     const float* __restrict__ b1,
                     const float* __restrict__ b2,
                     const float* __restrict__ w3,
                     const float* __restrict__ b3,
                     float* __restrict__ out) {
    extern __shared__ float smem[];
    float* h1T   = smem;                      // [128(j)][132]
    float* zred  = h1T + 128 * H1SR;          // [128(el)][9]
    float* b2s   = zred + EPB * 9;            // [128]
    float* w3s   = b2s + 128;                 // [128]
    float* b1s   = w3s + 128;                 // [128]
    float* w1rs  = b1s + 128;                 // [128]
    float* vals  = w1rs + 128;                // [128]
    float* zz    = vals + EPB;                // [128]
    int*   cols  = (int*)(zz + EPB);          // [128]

    const int tid = threadIdx.x;
    const int wid = tid >> 5;
    const int lane = tid & 31;
    const int base_node = blockIdx.x * NPB;
    const int e0 = blockIdx.x * EPB;

    // ---- stage b1/b2/w3, w1 value-row, colIdx, values ----
    if (tid < 128) {
        b2s[tid]  = b2[tid];
        w3s[tid]  = w3[tid];
        b1s[tid]  = b1[tid];
        w1rs[tid] = w1[256 * 128 + tid];
    } else if (tid < 256) {
        int t2 = tid - 128;
        cols[t2] = colIdx[e0 + t2];
        vals[t2] = values[e0 + t2];
    }
    __syncthreads();

    // ---- Phase 1: j across lanes (coalesced g_B rows), float4 stores ----
    {
        const int j = tid & 127;                 // feature, consecutive in warp
        const int g = tid >> 7;                  // 0..3 -> 2-node group
        const float b1j = b1s[j];
        const float wrj = w1rs[j];
#pragma unroll
        for (int nn = 0; nn < 2; ++nn) {
            const int node = g * 2 + nn;
            const float a = g_A[(base_node + node) * DIM + j] + b1j;
#pragma unroll
            for (int q = 0; q < 4; ++q) {
                const int el = node * 16 + q * 4;
                int4   c4 = *(const int4*)&cols[el];
                float4 v4 = *(const float4*)&vals[el];
                float4 h;
                h.x = fmaf(v4.x, wrj, a + g_B[c4.x * DIM + j]);
                h.y = fmaf(v4.y, wrj, a + g_B[c4.y * DIM + j]);
                h.z = fmaf(v4.z, wrj, a + g_B[c4.z * DIM + j]);
                h.w = fmaf(v4.w, wrj, a + g_B[c4.w * DIM + j]);
                h.x = fmaxf(h.x, 0.f); h.y = fmaxf(h.y, 0.f);
                h.z = fmaxf(h.z, 0.f); h.w = fmaxf(h.w, 0.f);
                *(float4*)&h1T[j * H1SR + el] = h;
            }
        }
    }
    __syncthreads();

    // ---- Phase 2: f32x2 GEMM; warp(eg,cg) tile = 64 edges x 16 cols ----
    {
        const int cg  = wid & 7;                // col group (16 cols)
        const int eg  = wid >> 3;               // edge half (0/1)
        const int jc0 = cg * 16;
        const int er0 = eg * 64 + lane * 2;     // 2 consecutive edges

        ull acc[2][8];
#pragma unroll
        for (int i = 0; i < 2; ++i)
#pragma unroll
            for (int p = 0; p < 8; ++p) acc[i][p] = 0ull;

#pragma unroll 1
        for (int k = 0; k < 128; ++k) {
            float2 a2 = *(const float2*)&h1T[k * H1SR + er0];
            ull pa0, pa1;
            PACK_F32X2(pa0, __float_as_uint(a2.x), __float_as_uint(a2.x));
            PACK_F32X2(pa1, __float_as_uint(a2.y), __float_as_uint(a2.y));

            const ulonglong2* wp = (const ulonglong2*)&c_w2[k * 128 + jc0];
            {
                ulonglong2 b01 = wp[0];
                FMA_F32X2(acc[0][0], pa0, b01.x);
                FMA_F32X2(acc[1][0], pa1, b01.x);
                FMA_F32X2(acc[0][1], pa0, b01.y);
                FMA_F32X2(acc[1][1], pa1, b01.y);
            }
            {
                ulonglong2 b23 = wp[1];
                FMA_F32X2(acc[0][2], pa0, b23.x);
                FMA_F32X2(acc[1][2], pa1, b23.x);
                FMA_F32X2(acc[0][3], pa0, b23.y);
                FMA_F32X2(acc[1][3], pa1, b23.y);
            }
            {
                ulonglong2 b45 = wp[2];
                FMA_F32X2(acc[0][4], pa0, b45.x);
                FMA_F32X2(acc[1][4], pa1, b45.x);
                FMA_F32X2(acc[0][5], pa0, b45.y);
                FMA_F32X2(acc[1][5], pa1, b45.y);
            }
            {
                ulonglong2 b67 = wp[3];
                FMA_F32X2(acc[0][6], pa0, b67.x);
                FMA_F32X2(acc[1][6], pa1, b67.x);
                FMA_F32X2(acc[0][7], pa0, b67.y);
                FMA_F32X2(acc[1][7], pa1, b67.y);
            }
        }

        // epilogue: unpack, +b2, relu, w3 partial dot (col-ascending order)
#pragma unroll
        for (int i = 0; i < 2; ++i) {
            float s = 0.f;
#pragma unroll
            for (int p = 0; p < 8; ++p) {
                unsigned lo, hi;
                UNPACK_F32X2(lo, hi, acc[i][p]);
                float h2a = fmaxf(__uint_as_float(lo) + b2s[jc0 + 2 * p], 0.f);
                s = fmaf(h2a, w3s[jc0 + 2 * p], s);
                float h2b = fmaxf(__uint_as_float(hi) + b2s[jc0 + 2 * p + 1], 0.f);
                s = fmaf(h2b, w3s[jc0 + 2 * p + 1], s);
            }
            zred[(er0 + i) * 9 + cg] = s;
        }
    }
    __syncthreads();

    if (tid < EPB) {
        float s = b3[0];
#pragma unroll
        for (int g = 0; g < 8; ++g) s += zred[tid * 9 + g];
        zz[tid] = s;
    }
    __syncthreads();

    // ---- Phase 3: warp w -> node w (first 8 warps), exact proven chain ----
    if (wid < 8) {
        const unsigned FULL = 0xffffffffu;
        const int l = lane & 15;
        const int el = wid * 16 + l;
        const float zv = zz[el];

        float m = zv;
#pragma unroll
        for (int o = 8; o >= 1; o >>= 1) m = fmaxf(m, __shfl_xor_sync(FULL, m, o, 16));
        float x1 = __fsub_rn(zv, m);
        float ev = (float)exp((double)x1);
        float s = 0.f;
#pragma unroll
        for (int o = 0; o < 16; ++o) s = __fadd_rn(s, __shfl_sync(FULL, ev, o, 16));
        float pi = __fdiv_rn(ev, s);

        float larg = __fadd_rn(pi, 1e-8f);
        float lg = (float)log((double)larg);
        float sx = __fdiv_rn(lg, temperature[0]);
        float hard = (float)(1.0 / (1.0 + exp(-(double)sx)));
        hard = fminf(fmaxf(hard, 0.f), 1.f);

        float m2 = hard;
#pragma unroll
        for (int o = 8; o >= 1; o >>= 1) m2 = fmaxf(m2, __shfl_xor_sync(FULL, m2, o, 16));
        float x2 = __fsub_rn(hard, m2);
        float e2 = (float)exp((double)x2);
        float s2 = 0.f;
#pragma unroll
        for (int o = 0; o < 16; ++o) s2 = __fadd_rn(s2, __shfl_sync(FULL, e2, o, 16));
        float y = __fdiv_rn(e2, s2);

        int r = 0;
#pragma unroll
        for (int o = 0; o < 16; ++o) {
            float yo = __shfl_sync(FULL, y, o, 16);
            r += (yo > y) || (yo == y && o < l);
        }
        unsigned bal = __ballot_sync(FULL, (r == 7) && (lane < 16));
        int src = __ffs(bal) - 1;
        float thre = __shfl_sync(FULL, y, src);

        float t = __fadd_rn(__fsub_rn(y, thre), 1e-7f);
        float outv = (t > 0.f) ? y : 0.f;
        if (lane < 16) out[e0 + el] = outv;
    }
}

// ---------------------------------------------------------------------------
extern "C" void kernel_launch(void* const* d_in, const int* in_sizes, int n_in,
                              void* d_out, int out_size) {
    const float* feat        = (const float*)d_in[0];
    const int*   indices     = (const int*)d_in[1];   // [2, E]
    const float* values      = (const float*)d_in[2]; // [E, 1]
    const float* temperature = (const float*)d_in[3];
    const float* w1          = (const float*)d_in[4]; // [257, 128]
    const float* b1          = (const float*)d_in[5];
    const float* w2          = (const float*)d_in[6]; // [128, 128]
    const float* b2          = (const float*)d_in[7];
    const float* w3          = (const float*)d_in[8]; // [128, 1]
    const float* b3          = (const float*)d_in[9];
    float* out = (float*)d_out;

    const int* colIdx = indices + EDGES;  // indices[1]

    // stage w2 into constant memory (device-to-device, graph-capturable)
    cudaMemcpyToSymbolAsync(c_w2, w2, HID * HID * sizeof(float), 0,
                            cudaMemcpyDeviceToDevice);

    const size_t smem1 = K1_SMEM_FLOATS * sizeof(float);
    const size_t smem2 = K2_SMEM_FLOATS * sizeof(float);
    cudaFuncSetAttribute(layer1_gemm_kernel,
                         cudaFuncAttributeMaxDynamicSharedMemorySize, (int)smem1);
    cudaFuncSetAttribute(edge_mlp_mask_kernel,
                         cudaFuncAttributeMaxDynamicSharedMemorySize, (int)smem2);

    dim3 g1((NN + 63) / 64, 2 * DIM / 64);  // 782 x 4
    layer1_gemm_kernel<<<g1, 256, smem1>>>(feat, w1);

    edge_mlp_mask_kernel<<<EDGES / EPB, K2T, smem2>>>(
        colIdx, values, temperature, w1, b1, b2, w3, b3, out);
}

// round 14
// speedup vs baseline: 1.9071x; 1.3545x over previous
#include <cuda_runtime.h>
#include <cuda_bf16.h>
#include <math.h>

// Problem constants (fixed by the dataset)
#define NN    50000
#define DEG   16
#define EDGES (NN * DEG)      // 800000
#define DIM   128
#define HID   128

#define NPB   8               // nodes per block (kernel 2)
#define EPB   128             // edges per block
#define K2T   512             // threads (kernel 2)
#define H1SR  132             // h1T row stride (floats)
#define W2HS  68              // smem w2-half row stride (floats, 272B = 16B-aligned)

typedef unsigned long long ull;

#define FMA_F32X2(acc, a, b) \
    asm("fma.rn.f32x2 %0, %1, %2, %0;" : "+l"(acc) : "l"(a), "l"(b))
#define PACK_F32X2(out, lo, hi) \
    asm("mov.b64 %0, {%1, %2};" : "=l"(out) : "r"(lo), "r"(hi))
#define UNPACK_F32X2(lo, hi, in) \
    asm("mov.b64 {%0, %1}, %2;" : "=r"(lo), "=r"(hi) : "l"(in))

// Persistent scratch: layer-1 node projections A = F @ W1[0:128], B = F @ W1[128:256]
__device__ float g_A[NN * DIM];
__device__ float g_B[NN * DIM];

// Layer-2 weights in constant memory (cols 0..63 consumed from here)
__constant__ float c_w2[HID * HID];   // 64 KB

// ---------------------------------------------------------------------------
// Kernel 1: AB = features[N,128] @ Wcat[128,256]. Tiled fp32 GEMM. (proven)
// ---------------------------------------------------------------------------
#define K1_SMEM_FLOATS (64 * 132 + 128 * 68)

__global__ void layer1_gemm_kernel(const float* __restrict__ feat,
                                   const float* __restrict__ w1) {
    extern __shared__ float smem1[];
    float* featS = smem1;              // [64][132]
    float* wS    = smem1 + 64 * 132;   // [128][68]

    const int tid = threadIdx.x;
    const int m0 = blockIdx.x * 64;
    const int n0 = blockIdx.y * 64;

    for (int t = tid; t < 64 * 32; t += 256) {
        int r = t >> 5, c4 = (t & 31) << 2;
        int gr = m0 + r;
        float4 v = make_float4(0.f, 0.f, 0.f, 0.f);
        if (gr < NN) v = *(const float4*)&feat[gr * DIM + c4];
        *(float4*)&featS[r * 132 + c4] = v;
    }
    for (int t = tid; t < 128 * 16; t += 256) {
        int k = t >> 4, c4 = (t & 15) << 2;
        int n = n0 + c4;
        const float* src = (n < 128) ? &w1[k * 128 + n]
                                     : &w1[(128 + k) * 128 + (n - 128)];
        *(float4*)&wS[k * 68 + c4] = *(const float4*)src;
    }
    __syncthreads();

    const int ty = tid >> 4, tx = tid & 15;
    const int r0 = ty * 4, c0 = tx * 4;
    float acc[4][4];
#pragma unroll
    for (int i = 0; i < 4; ++i)
#pragma unroll
        for (int j = 0; j < 4; ++j) acc[i][j] = 0.f;

#pragma unroll 4
    for (int k = 0; k < 128; ++k) {
        float a[4];
#pragma unroll
        for (int i = 0; i < 4; ++i) a[i] = featS[(r0 + i) * 132 + k];
        float4 bq = *(const float4*)&wS[k * 68 + c0];
        float b[4] = {bq.x, bq.y, bq.z, bq.w};
#pragma unroll
        for (int i = 0; i < 4; ++i)
#pragma unroll
            for (int j = 0; j < 4; ++j) acc[i][j] = fmaf(a[i], b[j], acc[i][j]);
    }

#pragma unroll
    for (int i = 0; i < 4; ++i) {
        int node = m0 + r0 + i;
        if (node >= NN) continue;
        int n = n0 + c0;
        float4 o = make_float4(acc[i][0], acc[i][1], acc[i][2], acc[i][3]);
        if (n < 128) *(float4*)&g_A[node * DIM + n] = o;
        else         *(float4*)&g_B[node * DIM + (n - 128)] = o;
    }
}

// ---------------------------------------------------------------------------
// Kernel 2: per block = 8 nodes = 128 edges, 512 threads, 2 blocks/SM.
//  Phase 2 b-operands split across ports: col-groups 0-3 from __constant__
//  (LDC port), col-groups 4-7 from an smem copy of w2 cols 64..127 (crossbar
//  broadcast). FMA pipe becomes the binder.
// ---------------------------------------------------------------------------
#define K2_SMEM_FLOATS (128 * H1SR + 128 * W2HS + EPB * 9 + 4 * 128 + 3 * EPB)

// GEMM inner loop over k for one warp tile (2 edges x 16 cols), b from BSRC.
// BSTRIDE in floats. Produces w3 partial dots into spart[2].
template <int BSTRIDE>
__device__ __forceinline__ void gemm_cols(const float* __restrict__ bsrc,
                                          const float* __restrict__ h1T,
                                          int er0, int jc0,
                                          const float* __restrict__ b2s,
                                          const float* __restrict__ w3s,
                                          float (&spart)[2]) {
    ull acc[2][8];
#pragma unroll
    for (int i = 0; i < 2; ++i)
#pragma unroll
        for (int p = 0; p < 8; ++p) acc[i][p] = 0ull;

#pragma unroll 1
    for (int k = 0; k < 128; ++k) {
        float2 a2 = *(const float2*)&h1T[k * H1SR + er0];
        ull pa0, pa1;
        PACK_F32X2(pa0, __float_as_uint(a2.x), __float_as_uint(a2.x));
        PACK_F32X2(pa1, __float_as_uint(a2.y), __float_as_uint(a2.y));

        const ulonglong2* wp = (const ulonglong2*)&bsrc[k * BSTRIDE];
        {
            ulonglong2 b01 = wp[0];
            FMA_F32X2(acc[0][0], pa0, b01.x);
            FMA_F32X2(acc[1][0], pa1, b01.x);
            FMA_F32X2(acc[0][1], pa0, b01.y);
            FMA_F32X2(acc[1][1], pa1, b01.y);
        }
        {
            ulonglong2 b23 = wp[1];
            FMA_F32X2(acc[0][2], pa0, b23.x);
            FMA_F32X2(acc[1][2], pa1, b23.x);
            FMA_F32X2(acc[0][3], pa0, b23.y);
            FMA_F32X2(acc[1][3], pa1, b23.y);
        }
        {
            ulonglong2 b45 = wp[2];
            FMA_F32X2(acc[0][4], pa0, b45.x);
            FMA_F32X2(acc[1][4], pa1, b45.x);
            FMA_F32X2(acc[0][5], pa0, b45.y);
            FMA_F32X2(acc[1][5], pa1, b45.y);
        }
        {
            ulonglong2 b67 = wp[3];
            FMA_F32X2(acc[0][6], pa0, b67.x);
            FMA_F32X2(acc[1][6], pa1, b67.x);
            FMA_F32X2(acc[0][7], pa0, b67.y);
            FMA_F32X2(acc[1][7], pa1, b67.y);
        }
    }

    // epilogue: unpack, +b2, relu, w3 partial dot (col-ascending order)
#pragma unroll
    for (int i = 0; i < 2; ++i) {
        float s = 0.f;
#pragma unroll
        for (int p = 0; p < 8; ++p) {
            unsigned lo, hi;
            UNPACK_F32X2(lo, hi, acc[i][p]);
            float h2a = fmaxf(__uint_as_float(lo) + b2s[jc0 + 2 * p], 0.f);
            s = fmaf(h2a, w3s[jc0 + 2 * p], s);
            float h2b = fmaxf(__uint_as_float(hi) + b2s[jc0 + 2 * p + 1], 0.f);
            s = fmaf(h2b, w3s[jc0 + 2 * p + 1], s);
        }
        spart[i] = s;
    }
}

__global__ void __launch_bounds__(K2T, 2)
edge_mlp_mask_kernel(const int* __restrict__ colIdx,
                     const float* __restrict__ values,
                     const float* __restrict__ temperature,
                     const float* __restrict__ w1,
                     const float* __restrict__ b1,
                     const float* __restrict__ w2g,
                     const float* __restrict__ b2,
                     const float* __restrict__ w3,
                     const float* __restrict__ b3,
                     float* __restrict__ out) {
    extern __shared__ float smem[];
    float* h1T   = smem;                      // [128(j)][132]
    float* w2h   = h1T + 128 * H1SR;          // [128(k)][68] cols 64..127
    float* zred  = w2h + 128 * W2HS;          // [128(el)][9]
    float* b2s   = zred + EPB * 9;            // [128]
    float* w3s   = b2s + 128;                 // [128]
    float* b1s   = w3s + 128;                 // [128]
    float* w1rs  = b1s + 128;                 // [128]
    float* vals  = w1rs + 128;                // [128]
    float* zz    = vals + EPB;                // [128]
    int*   cols  = (int*)(zz + EPB);          // [128]

    const int tid = threadIdx.x;
    const int wid = tid >> 5;
    const int lane = tid & 31;
    const int base_node = blockIdx.x * NPB;
    const int e0 = blockIdx.x * EPB;

    // ---- stage w2 cols 64..127 into smem (128 k x 64 cols, float4) ----
    for (int t = tid; t < 128 * 16; t += K2T) {
        int k = t >> 4, c4 = (t & 15) << 2;
        *(float4*)&w2h[k * W2HS + c4] = *(const float4*)&w2g[k * 128 + 64 + c4];
    }
    // ---- stage b1/b2/w3, w1 value-row, colIdx, values ----
    if (tid < 128) {
        b2s[tid]  = b2[tid];
        w3s[tid]  = w3[tid];
        b1s[tid]  = b1[tid];
        w1rs[tid] = w1[256 * 128 + tid];
    } else if (tid < 256) {
        int t2 = tid - 128;
        cols[t2] = colIdx[e0 + t2];
        vals[t2] = values[e0 + t2];
    }
    __syncthreads();

    // ---- Phase 1: j across lanes (coalesced g_B rows), float4 stores ----
    {
        const int j = tid & 127;                 // feature, consecutive in warp
        const int g = tid >> 7;                  // 0..3 -> 2-node group
        const float b1j = b1s[j];
        const float wrj = w1rs[j];
#pragma unroll
        for (int nn = 0; nn < 2; ++nn) {
            const int node = g * 2 + nn;
            const float a = g_A[(base_node + node) * DIM + j] + b1j;
#pragma unroll
            for (int q = 0; q < 4; ++q) {
                const int el = node * 16 + q * 4;
                int4   c4 = *(const int4*)&cols[el];
                float4 v4 = *(const float4*)&vals[el];
                float4 h;
                h.x = fmaf(v4.x, wrj, a + g_B[c4.x * DIM + j]);
                h.y = fmaf(v4.y, wrj, a + g_B[c4.y * DIM + j]);
                h.z = fmaf(v4.z, wrj, a + g_B[c4.z * DIM + j]);
                h.w = fmaf(v4.w, wrj, a + g_B[c4.w * DIM + j]);
                h.x = fmaxf(h.x, 0.f); h.y = fmaxf(h.y, 0.f);
                h.z = fmaxf(h.z, 0.f); h.w = fmaxf(h.w, 0.f);
                *(float4*)&h1T[j * H1SR + el] = h;
            }
        }
    }
    __syncthreads();

    // ---- Phase 2: f32x2 GEMM, b split across const port and smem crossbar --
    {
        const int cg  = wid & 7;                // col group (16 cols)
        const int eg  = wid >> 3;               // edge half (0/1)
        const int jc0 = cg * 16;
        const int er0 = eg * 64 + lane * 2;     // 2 consecutive edges

        float spart[2];
        if (cg < 4) {
            gemm_cols<128>(&c_w2[jc0], h1T, er0, jc0, b2s, w3s, spart);
        } else {
            gemm_cols<W2HS>(&w2h[jc0 - 64], h1T, er0, jc0, b2s, w3s, spart);
        }
#pragma unroll
        for (int i = 0; i < 2; ++i)
            zred[(er0 + i) * 9 + cg] = spart[i];
    }
    __syncthreads();

    if (tid < EPB) {
        float s = b3[0];
#pragma unroll
        for (int g = 0; g < 8; ++g) s += zred[tid * 9 + g];
        zz[tid] = s;
    }
    __syncthreads();

    // ---- Phase 3: warp w -> node w (first 8 warps), exact proven chain ----
    if (wid < 8) {
        const unsigned FULL = 0xffffffffu;
        const int l = lane & 15;
        const int el = wid * 16 + l;
        const float zv = zz[el];

        float m = zv;
#pragma unroll
        for (int o = 8; o >= 1; o >>= 1) m = fmaxf(m, __shfl_xor_sync(FULL, m, o, 16));
        float x1 = __fsub_rn(zv, m);
        float ev = (float)exp((double)x1);
        float s = 0.f;
#pragma unroll
        for (int o = 0; o < 16; ++o) s = __fadd_rn(s, __shfl_sync(FULL, ev, o, 16));
        float pi = __fdiv_rn(ev, s);

        float larg = __fadd_rn(pi, 1e-8f);
        float lg = (float)log((double)larg);
        float sx = __fdiv_rn(lg, temperature[0]);
        float hard = (float)(1.0 / (1.0 + exp(-(double)sx)));
        hard = fminf(fmaxf(hard, 0.f), 1.f);

        float m2 = hard;
#pragma unroll
        for (int o = 8; o >= 1; o >>= 1) m2 = fmaxf(m2, __shfl_xor_sync(FULL, m2, o, 16));
        float x2 = __fsub_rn(hard, m2);
        float e2 = (float)exp((double)x2);
        float s2 = 0.f;
#pragma unroll
        for (int o = 0; o < 16; ++o) s2 = __fadd_rn(s2, __shfl_sync(FULL, e2, o, 16));
        float y = __fdiv_rn(e2, s2);

        int r = 0;
#pragma unroll
        for (int o = 0; o < 16; ++o) {
            float yo = __shfl_sync(FULL, y, o, 16);
            r += (yo > y) || (yo == y && o < l);
        }
        unsigned bal = __ballot_sync(FULL, (r == 7) && (lane < 16));
        int src = __ffs(bal) - 1;
        float thre = __shfl_sync(FULL, y, src);

        float t = __fadd_rn(__fsub_rn(y, thre), 1e-7f);
        float outv = (t > 0.f) ? y : 0.f;
        if (lane < 16) out[e0 + el] = outv;
    }
}

// ---------------------------------------------------------------------------
extern "C" void kernel_launch(void* const* d_in, const int* in_sizes, int n_in,
                              void* d_out, int out_size) {
    const float* feat        = (const float*)d_in[0];
    const int*   indices     = (const int*)d_in[1];   // [2, E]
    const float* values      = (const float*)d_in[2]; // [E, 1]
    const float* temperature = (const float*)d_in[3];
    const float* w1          = (const float*)d_in[4]; // [257, 128]
    const float* b1          = (const float*)d_in[5];
    const float* w2          = (const float*)d_in[6]; // [128, 128]
    const float* b2          = (const float*)d_in[7];
    const float* w3          = (const float*)d_in[8]; // [128, 1]
    const float* b3          = (const float*)d_in[9];
    float* out = (float*)d_out;

    const int* colIdx = indices + EDGES;  // indices[1]

    // stage w2 into constant memory (device-to-device, graph-capturable)
    cudaMemcpyToSymbolAsync(c_w2, w2, HID * HID * sizeof(float), 0,
                            cudaMemcpyDeviceToDevice);

    const size_t smem1 = K1_SMEM_FLOATS * sizeof(float);
    const size_t smem2 = K2_SMEM_FLOATS * sizeof(float);
    cudaFuncSetAttribute(layer1_gemm_kernel,
                         cudaFuncAttributeMaxDynamicSharedMemorySize, (int)smem1);
    cudaFuncSetAttribute(edge_mlp_mask_kernel,
                         cudaFuncAttributeMaxDynamicSharedMemorySize, (int)smem2);

    dim3 g1((NN + 63) / 64, 2 * DIM / 64);  // 782 x 4
    layer1_gemm_kernel<<<g1, 256, smem1>>>(feat, w1);

    edge_mlp_mask_kernel<<<EDGES / EPB, K2T, smem2>>>(
        colIdx, values, temperature, w1, b1, w2, b2, w3, b3, out);
}

// round 15
// speedup vs baseline: 2.3506x; 1.2326x over previous
#include <cuda_runtime.h>
#include <cuda_bf16.h>
#include <math.h>

// Problem constants (fixed by the dataset)
#define NN    50000
#define DEG   16
#define EDGES (NN * DEG)      // 800000
#define DIM   128
#define HID   128

#define NPB   8               // nodes per block (kernel 2)
#define EPB   128             // edges per block
#define K2T   256             // threads (kernel 2)
#define H1SR  132             // h1T row stride (floats)
#define W2HS  68              // smem w2-half row stride (floats, 272B)

typedef unsigned long long ull;

#define FMA_F32X2(acc, a, b) \
    asm("fma.rn.f32x2 %0, %1, %2, %0;" : "+l"(acc) : "l"(a), "l"(b))
#define PACK_F32X2(out, lo, hi) \
    asm("mov.b64 %0, {%1, %2};" : "=l"(out) : "r"(lo), "r"(hi))
#define UNPACK_F32X2(lo, hi, in) \
    asm("mov.b64 {%0, %1}, %2;" : "=r"(lo), "=r"(hi) : "l"(in))

// Persistent scratch: layer-1 node projections A = F @ W1[0:128], B = F @ W1[128:256]
__device__ float g_A[NN * DIM];
__device__ float g_B[NN * DIM];

// Layer-2 weights in constant memory (cols 0..63 consumed from here)
__constant__ float c_w2[HID * HID];   // 64 KB

// ---------------------------------------------------------------------------
// Kernel 1: AB = features[N,128] @ Wcat[128,256]. f32x2-packed fp32 GEMM.
// Column-pair packing: each FFMA2 computes two output columns' FMAs; the
// per-output k-order is unchanged -> results bit-identical to scalar version.
// ---------------------------------------------------------------------------
#define K1_SMEM_FLOATS (64 * 132 + 128 * 68)

__global__ void layer1_gemm_kernel(const float* __restrict__ feat,
                                   const float* __restrict__ w1) {
    extern __shared__ float smem1[];
    float* featS = smem1;              // [64][132]
    float* wS    = smem1 + 64 * 132;   // [128][68]

    const int tid = threadIdx.x;
    const int m0 = blockIdx.x * 64;
    const int n0 = blockIdx.y * 64;

    for (int t = tid; t < 64 * 32; t += 256) {
        int r = t >> 5, c4 = (t & 31) << 2;
        int gr = m0 + r;
        float4 v = make_float4(0.f, 0.f, 0.f, 0.f);
        if (gr < NN) v = *(const float4*)&feat[gr * DIM + c4];
        *(float4*)&featS[r * 132 + c4] = v;
    }
    for (int t = tid; t < 128 * 16; t += 256) {
        int k = t >> 4, c4 = (t & 15) << 2;
        int n = n0 + c4;
        const float* src = (n < 128) ? &w1[k * 128 + n]
                                     : &w1[(128 + k) * 128 + (n - 128)];
        *(float4*)&wS[k * 68 + c4] = *(const float4*)src;
    }
    __syncthreads();

    const int ty = tid >> 4, tx = tid & 15;
    const int r0 = ty * 4, c0 = tx * 4;          // c0 multiple of 4 -> 16B aligned
    ull acc[4][2];
#pragma unroll
    for (int i = 0; i < 4; ++i) { acc[i][0] = 0ull; acc[i][1] = 0ull; }

#pragma unroll 2
    for (int k = 0; k < 128; ++k) {
        ulonglong2 bq = *(const ulonglong2*)&wS[k * 68 + c0];  // cols (c0,c0+1),(c0+2,c0+3)
        float a0 = featS[(r0 + 0) * 132 + k];
        float a1 = featS[(r0 + 1) * 132 + k];
        float a2 = featS[(r0 + 2) * 132 + k];
        float a3 = featS[(r0 + 3) * 132 + k];
        ull pa[4];
        PACK_F32X2(pa[0], __float_as_uint(a0), __float_as_uint(a0));
        PACK_F32X2(pa[1], __float_as_uint(a1), __float_as_uint(a1));
        PACK_F32X2(pa[2], __float_as_uint(a2), __float_as_uint(a2));
        PACK_F32X2(pa[3], __float_as_uint(a3), __float_as_uint(a3));
#pragma unroll
        for (int i = 0; i < 4; ++i) {
            FMA_F32X2(acc[i][0], pa[i], bq.x);
            FMA_F32X2(acc[i][1], pa[i], bq.y);
        }
    }

#pragma unroll
    for (int i = 0; i < 4; ++i) {
        int node = m0 + r0 + i;
        if (node >= NN) continue;
        int n = n0 + c0;
        unsigned l0, h0, l1, h1;
        UNPACK_F32X2(l0, h0, acc[i][0]);
        UNPACK_F32X2(l1, h1, acc[i][1]);
        float4 o = make_float4(__uint_as_float(l0), __uint_as_float(h0),
                               __uint_as_float(l1), __uint_as_float(h1));
        if (n < 128) *(float4*)&g_A[node * DIM + n] = o;
        else         *(float4*)&g_B[node * DIM + (n - 128)] = o;
    }
}

// ---------------------------------------------------------------------------
// Kernel 2: per block = 8 nodes = 128 edges, 256 threads (8 warps), 2 blk/SM.
//  Warp tile = 128 edges x 16 cols (thread: 4 edges x 16 cols, acc = 64 regs).
//  b split across ports: col-groups 0-3 from __constant__, 4-7 from smem.
//  128-reg budget gives ptxas room to pipeline the LDS/LDC chains.
// ---------------------------------------------------------------------------
#define K2_SMEM_FLOATS (128 * H1SR + 128 * W2HS + EPB * 9 + 4 * 128 + 3 * EPB)

template <int BSTRIDE>
__device__ __forceinline__ void gemm_cols4(const float* __restrict__ bsrc,
                                           const float* __restrict__ h1T,
                                           int er0, int jc0,
                                           const float* __restrict__ b2s,
                                           const float* __restrict__ w3s,
                                           float (&spart)[4]) {
    ull acc[4][8];
#pragma unroll
    for (int i = 0; i < 4; ++i)
#pragma unroll
        for (int p = 0; p < 8; ++p) acc[i][p] = 0ull;

#pragma unroll 2
    for (int k = 0; k < 128; ++k) {
        float4 a4 = *(const float4*)&h1T[k * H1SR + er0];
        ull pa[4];
        PACK_F32X2(pa[0], __float_as_uint(a4.x), __float_as_uint(a4.x));
        PACK_F32X2(pa[1], __float_as_uint(a4.y), __float_as_uint(a4.y));
        PACK_F32X2(pa[2], __float_as_uint(a4.z), __float_as_uint(a4.z));
        PACK_F32X2(pa[3], __float_as_uint(a4.w), __float_as_uint(a4.w));

        const ulonglong2* wp = (const ulonglong2*)&bsrc[k * BSTRIDE];
        {
            ulonglong2 b01 = wp[0];
#pragma unroll
            for (int i = 0; i < 4; ++i) {
                FMA_F32X2(acc[i][0], pa[i], b01.x);
                FMA_F32X2(acc[i][1], pa[i], b01.y);
            }
        }
        {
            ulonglong2 b23 = wp[1];
#pragma unroll
            for (int i = 0; i < 4; ++i) {
                FMA_F32X2(acc[i][2], pa[i], b23.x);
                FMA_F32X2(acc[i][3], pa[i], b23.y);
            }
        }
        {
            ulonglong2 b45 = wp[2];
#pragma unroll
            for (int i = 0; i < 4; ++i) {
                FMA_F32X2(acc[i][4], pa[i], b45.x);
                FMA_F32X2(acc[i][5], pa[i], b45.y);
            }
        }
        {
            ulonglong2 b67 = wp[3];
#pragma unroll
            for (int i = 0; i < 4; ++i) {
                FMA_F32X2(acc[i][6], pa[i], b67.x);
                FMA_F32X2(acc[i][7], pa[i], b67.y);
            }
        }
    }

    // epilogue: unpack, +b2, relu, w3 partial dot (col-ascending order)
#pragma unroll
    for (int i = 0; i < 4; ++i) {
        float s = 0.f;
#pragma unroll
        for (int p = 0; p < 8; ++p) {
            unsigned lo, hi;
            UNPACK_F32X2(lo, hi, acc[i][p]);
            float h2a = fmaxf(__uint_as_float(lo) + b2s[jc0 + 2 * p], 0.f);
            s = fmaf(h2a, w3s[jc0 + 2 * p], s);
            float h2b = fmaxf(__uint_as_float(hi) + b2s[jc0 + 2 * p + 1], 0.f);
            s = fmaf(h2b, w3s[jc0 + 2 * p + 1], s);
        }
        spart[i] = s;
    }
}

__global__ void __launch_bounds__(K2T, 2)
edge_mlp_mask_kernel(const int* __restrict__ colIdx,
                     const float* __restrict__ values,
                     const float* __restrict__ temperature,
                     const float* __restrict__ w1,
                     const float* __restrict__ b1,
                     const float* __restrict__ w2g,
                     const float* __restrict__ b2,
                     const float* __restrict__ w3,
                     const float* __restrict__ b3,
                     float* __restrict__ out) {
    extern __shared__ float smem[];
    float* h1T   = smem;                      // [128(j)][132]
    float* w2h   = h1T + 128 * H1SR;          // [128(k)][68] cols 64..127
    float* zred  = w2h + 128 * W2HS;          // [128(el)][9]
    float* b2s   = zred + EPB * 9;            // [128]
    float* w3s   = b2s + 128;                 // [128]
    float* b1s   = w3s + 128;                 // [128]
    float* w1rs  = b1s + 128;                 // [128]
    float* vals  = w1rs + 128;                // [128]
    float* zz    = vals + EPB;                // [128]
    int*   cols  = (int*)(zz + EPB);          // [128]

    const int tid = threadIdx.x;
    const int wid = tid >> 5;
    const int lane = tid & 31;
    const int base_node = blockIdx.x * NPB;
    const int e0 = blockIdx.x * EPB;

    // ---- stage w2 cols 64..127 into smem ----
    for (int t = tid; t < 128 * 16; t += K2T) {
        int k = t >> 4, c4 = (t & 15) << 2;
        *(float4*)&w2h[k * W2HS + c4] = *(const float4*)&w2g[k * 128 + 64 + c4];
    }
    // ---- stage b1/b2/w3, w1 value-row, colIdx, values ----
    if (tid < 128) {
        b2s[tid]  = b2[tid];
        w3s[tid]  = w3[tid];
        b1s[tid]  = b1[tid];
        w1rs[tid] = w1[256 * 128 + tid];
    } else {
        int t2 = tid - 128;
        cols[t2] = colIdx[e0 + t2];
        vals[t2] = values[e0 + t2];
    }
    __syncthreads();

    // ---- Phase 1: j across lanes (coalesced g_B rows), float4 stores ----
    {
        const int j = tid & 127;                 // feature, consecutive in warp
        const int g = tid >> 7;                  // 0/1 -> 4-node group
        const float b1j = b1s[j];
        const float wrj = w1rs[j];
#pragma unroll
        for (int nn = 0; nn < 4; ++nn) {
            const int node = g * 4 + nn;
            const float a = g_A[(base_node + node) * DIM + j] + b1j;
#pragma unroll
            for (int q = 0; q < 4; ++q) {
                const int el = node * 16 + q * 4;
                int4   c4 = *(const int4*)&cols[el];
                float4 v4 = *(const float4*)&vals[el];
                float4 h;
                h.x = fmaf(v4.x, wrj, a + g_B[c4.x * DIM + j]);
                h.y = fmaf(v4.y, wrj, a + g_B[c4.y * DIM + j]);
                h.z = fmaf(v4.z, wrj, a + g_B[c4.z * DIM + j]);
                h.w = fmaf(v4.w, wrj, a + g_B[c4.w * DIM + j]);
                h.x = fmaxf(h.x, 0.f); h.y = fmaxf(h.y, 0.f);
                h.z = fmaxf(h.z, 0.f); h.w = fmaxf(h.w, 0.f);
                *(float4*)&h1T[j * H1SR + el] = h;
            }
        }
    }
    __syncthreads();

    // ---- Phase 2: f32x2 GEMM; warp = 16-col group over all 128 edges ----
    {
        const int cg  = wid;                    // col group (16 cols)
        const int jc0 = cg * 16;
        const int er0 = lane * 4;               // 4 consecutive edges

        float spart[4];
        if (cg < 4) {
            gemm_cols4<128>(&c_w2[jc0], h1T, er0, jc0, b2s, w3s, spart);
        } else {
            gemm_cols4<W2HS>(&w2h[jc0 - 64], h1T, er0, jc0, b2s, w3s, spart);
        }
#pragma unroll
        for (int i = 0; i < 4; ++i)
            zred[(er0 + i) * 9 + cg] = spart[i];
    }
    __syncthreads();

    if (tid < EPB) {
        float s = b3[0];
#pragma unroll
        for (int g = 0; g < 8; ++g) s += zred[tid * 9 + g];
        zz[tid] = s;
    }
    __syncthreads();

    // ---- Phase 3: warp w -> node w (8 warps), exact proven chain ----
    {
        const unsigned FULL = 0xffffffffu;
        const int l = lane & 15;
        const int el = wid * 16 + l;
        const float zv = zz[el];

        float m = zv;
#pragma unroll
        for (int o = 8; o >= 1; o >>= 1) m = fmaxf(m, __shfl_xor_sync(FULL, m, o, 16));
        float x1 = __fsub_rn(zv, m);
        float ev = (float)exp((double)x1);
        float s = 0.f;
#pragma unroll
        for (int o = 0; o < 16; ++o) s = __fadd_rn(s, __shfl_sync(FULL, ev, o, 16));
        float pi = __fdiv_rn(ev, s);

        float larg = __fadd_rn(pi, 1e-8f);
        float lg = (float)log((double)larg);
        float sx = __fdiv_rn(lg, temperature[0]);
        float hard = (float)(1.0 / (1.0 + exp(-(double)sx)));
        hard = fminf(fmaxf(hard, 0.f), 1.f);

        float m2 = hard;
#pragma unroll
        for (int o = 8; o >= 1; o >>= 1) m2 = fmaxf(m2, __shfl_xor_sync(FULL, m2, o, 16));
        float x2 = __fsub_rn(hard, m2);
        float e2 = (float)exp((double)x2);
        float s2 = 0.f;
#pragma unroll
        for (int o = 0; o < 16; ++o) s2 = __fadd_rn(s2, __shfl_sync(FULL, e2, o, 16));
        float y = __fdiv_rn(e2, s2);

        int r = 0;
#pragma unroll
        for (int o = 0; o < 16; ++o) {
            float yo = __shfl_sync(FULL, y, o, 16);
            r += (yo > y) || (yo == y && o < l);
        }
        unsigned bal = __ballot_sync(FULL, (r == 7) && (lane < 16));
        int src = __ffs(bal) - 1;
        float thre = __shfl_sync(FULL, y, src);

        float t = __fadd_rn(__fsub_rn(y, thre), 1e-7f);
        float outv = (t > 0.f) ? y : 0.f;
        if (lane < 16) out[e0 + el] = outv;
    }
}

// ---------------------------------------------------------------------------
extern "C" void kernel_launch(void* const* d_in, const int* in_sizes, int n_in,
                              void* d_out, int out_size) {
    const float* feat        = (const float*)d_in[0];
    const int*   indices     = (const int*)d_in[1];   // [2, E]
    const float* values      = (const float*)d_in[2]; // [E, 1]
    const float* temperature = (const float*)d_in[3];
    const float* w1          = (const float*)d_in[4]; // [257, 128]
    const float* b1          = (const float*)d_in[5];
    const float* w2          = (const float*)d_in[6]; // [128, 128]
    const float* b2          = (const float*)d_in[7];
    const float* w3          = (const float*)d_in[8]; // [128, 1]
    const float* b3          = (const float*)d_in[9];
    float* out = (float*)d_out;

    const int* colIdx = indices + EDGES;  // indices[1]

    // stage w2 into constant memory (device-to-device, graph-capturable)
    cudaMemcpyToSymbolAsync(c_w2, w2, HID * HID * sizeof(float), 0,
                            cudaMemcpyDeviceToDevice);

    const size_t smem1 = K1_SMEM_FLOATS * sizeof(float);
    const size_t smem2 = K2_SMEM_FLOATS * sizeof(float);
    cudaFuncSetAttribute(layer1_gemm_kernel,
                         cudaFuncAttributeMaxDynamicSharedMemorySize, (int)smem1);
    cudaFuncSetAttribute(edge_mlp_mask_kernel,
                         cudaFuncAttributeMaxDynamicSharedMemorySize, (int)smem2);

    dim3 g1((NN + 63) / 64, 2 * DIM / 64);  // 782 x 4
    layer1_gemm_kernel<<<g1, 256, smem1>>>(feat, w1);

    edge_mlp_mask_kernel<<<EDGES / EPB, K2T, smem2>>>(
        colIdx, values, temperature, w1, b1, w2, b2, w3, b3, out);
}